// round 1
// baseline (speedup 1.0000x reference)
#include <cuda_runtime.h>
#include <math.h>

#define Bv   64
#define Sv   1024
#define Hv   1024
#define Ev   512
#define Vv   50257
#define D2H  2048
#define D3H  3072
#define XK   3584   // 2H + E + H  (x_in cols 0..2559, hidden cols 2560..3583)
#define G4H  4096
#define SPLITS 16
#define ROWS  (Sv / SPLITS)   // 64

// ---------------- scratch (device globals; no runtime allocation) ----------
__device__ float g_partial_l[Bv * SPLITS];
__device__ float g_partial_acc[(size_t)Bv * SPLITS * D2H];   // 8 MB
__device__ float g_xfull[Bv * XK];
__device__ float g_gparts[4 * Bv * G4H];                      // 4 MB (split-K partials)

// =============================================================
// Kernel 1: fused attention, single streaming pass over encoder.
// grid (SPLITS, B), 256 threads. Each thread owns 8 feature cols.
// Unnormalized softmax (energies bounded, exp safe): accumulate
// l = sum exp(e), acc[c] = sum exp(e)*enc[c] per S-chunk.
// =============================================================
__global__ void __launch_bounds__(256) attn_kernel(
    const float* __restrict__ enc, const float* __restrict__ hidden,
    const float* __restrict__ We, const float* __restrict__ be_p)
{
    const int b = blockIdx.y, sp = blockIdx.x, t = threadIdx.x;
    const int lane = t & 31, wid = t >> 5;
    __shared__ float red[8];
    __shared__ float s_bias;

    float wreg[8];
#pragma unroll
    for (int k = 0; k < 8; k++) wreg[k] = We[k * 256 + t];

    // hidden-part bias: dot(hidden[b], We[2H:3H]) + be  (constant over s)
    float pb = 0.f;
#pragma unroll
    for (int k = 0; k < 4; k++) pb += hidden[b * Hv + k * 256 + t] * We[D2H + k * 256 + t];
#pragma unroll
    for (int o = 16; o > 0; o >>= 1) pb += __shfl_xor_sync(0xffffffffu, pb, o);
    if (lane == 0) red[wid] = pb;
    __syncthreads();
    if (t == 0) {
        float s = 0.f;
#pragma unroll
        for (int w = 0; w < 8; w++) s += red[w];
        s_bias = s + be_p[0];
    }
    __syncthreads();
    const float hbias = s_bias;

    float acc[8] = {0.f,0.f,0.f,0.f,0.f,0.f,0.f,0.f};
    float lsum = 0.f;
    const float* encb = enc + ((size_t)(b * Sv + sp * ROWS)) * D2H;

    for (int s = 0; s < ROWS; s++) {
        const float* row = encb + (size_t)s * D2H;
        float ev[8];
#pragma unroll
        for (int k = 0; k < 8; k++) ev[k] = row[k * 256 + t];
        float pd = 0.f;
#pragma unroll
        for (int k = 0; k < 8; k++) pd += ev[k] * wreg[k];
#pragma unroll
        for (int o = 16; o > 0; o >>= 1) pd += __shfl_xor_sync(0xffffffffu, pd, o);
        if (lane == 0) red[wid] = pd;
        __syncthreads();
        float dot = red[0]+red[1]+red[2]+red[3]+red[4]+red[5]+red[6]+red[7] + hbias;
        __syncthreads();
        float e = dot > 0.f ? dot : 0.f;   // relu
        float w = expf(e);
        lsum += w;
#pragma unroll
        for (int k = 0; k < 8; k++) acc[k] += w * ev[k];
    }

    float* pacc = g_partial_acc + ((size_t)(b * SPLITS + sp)) * D2H;
#pragma unroll
    for (int k = 0; k < 8; k++) pacc[k * 256 + t] = acc[k];
    if (t == 0) g_partial_l[b * SPLITS + sp] = lsum;
}

// =============================================================
// Kernel 2: combine attention partials -> c_i; build x_full =
// [c_i(2048) | emb[x_tok](512) | hidden(1024)].  grid (B), 256 thr.
// =============================================================
__global__ void __launch_bounds__(256) combine_kernel(
    const float* __restrict__ hidden, const float* __restrict__ emb,
    const int* __restrict__ x_tok)
{
    const int b = blockIdx.x, t = threadIdx.x;
    __shared__ float s_inv;
    if (t == 0) {
        float s = 0.f;
#pragma unroll
        for (int i = 0; i < SPLITS; i++) s += g_partial_l[b * SPLITS + i];
        s_inv = 1.f / s;
    }
    __syncthreads();
    const float inv = s_inv;
    for (int c = t; c < D2H; c += 256) {
        float s = 0.f;
#pragma unroll
        for (int i = 0; i < SPLITS; i++)
            s += g_partial_acc[((size_t)(b * SPLITS + i)) * D2H + c];
        g_xfull[b * XK + c] = s * inv;
    }
    const int tok = x_tok[b];
    for (int j = t; j < Ev; j += 256)
        g_xfull[b * XK + D2H + j] = emb[(size_t)tok * Ev + j];
    for (int j = t; j < Hv; j += 256)
        g_xfull[b * XK + D2H + Ev + j] = hidden[b * Hv + j];
}

// =============================================================
// Kernel 3: gates GEMM  [64 x 4096] = x_full[64 x 3584] * W^T
// split-K = 4 (k ranges of 896), BN=64, BK=32, 256 thr, 4x4 tiles.
// Writes split partials (deterministic; no atomics).
// =============================================================
__global__ void __launch_bounds__(256) gates_gemm(
    const float* __restrict__ W_ih, const float* __restrict__ W_hh)
{
    const int nt = blockIdx.x;   // 0..63 (o tile of 64)
    const int ks = blockIdx.y;   // 0..3
    const int t  = threadIdx.x;
    __shared__ float xs[32][68];
    __shared__ float ws[32][68];
    const int tb = (t & 15) * 4;
    const int to = (t >> 4) * 4;
    float acc[4][4] = {};
    const int k0base = ks * 896;

    for (int kc = 0; kc < 28; kc++) {
        const int kbase = k0base + kc * 32;
#pragma unroll
        for (int i = 0; i < 8; i++) {
            int e = t + 256 * i;
            int bb = e >> 5, kk = e & 31;
            xs[kk][bb] = g_xfull[bb * XK + kbase + kk];
        }
#pragma unroll
        for (int i = 0; i < 8; i++) {
            int e = t + 256 * i;
            int oo = e >> 5, kk = e & 31;
            int og = nt * 64 + oo;
            int kg = kbase + kk;
            float wv;
            if (kg < 2560) wv = W_ih[(size_t)og * 2560 + kg];
            else           wv = W_hh[(size_t)og * 1024 + (kg - 2560)];
            ws[kk][oo] = wv;
        }
        __syncthreads();
#pragma unroll
        for (int kk = 0; kk < 32; kk++) {
            float4 xr = *(const float4*)&xs[kk][tb];
            float4 wr = *(const float4*)&ws[kk][to];
            float xv[4] = {xr.x, xr.y, xr.z, xr.w};
            float wv[4] = {wr.x, wr.y, wr.z, wr.w};
#pragma unroll
            for (int i = 0; i < 4; i++)
#pragma unroll
                for (int j = 0; j < 4; j++) acc[i][j] += xv[i] * wv[j];
        }
        __syncthreads();
    }
    float* gp = g_gparts + (size_t)ks * (Bv * G4H);
#pragma unroll
    for (int i = 0; i < 4; i++)
#pragma unroll
        for (int j = 0; j < 4; j++)
            gp[(tb + i) * G4H + nt * 64 + to + j] = acc[i][j];
}

// =============================================================
// Kernel 4: sum split-K partials + biases, LSTM pointwise.
// Writes h_next, c_next into d_out tail regions. grid (B), 256 thr.
// =============================================================
__global__ void __launch_bounds__(256) lstm_kernel(
    const float* __restrict__ cell, const float* __restrict__ b_ih,
    const float* __restrict__ b_hh, float* __restrict__ out)
{
    const int b = blockIdx.x, t = threadIdx.x;
    float* h_out = out + (size_t)Bv * Vv;
    float* c_out = h_out + Bv * Hv;
    for (int h = t; h < Hv; h += 256) {
        const int base = b * G4H;
        float gi = 0.f, gf = 0.f, gg = 0.f, go = 0.f;
#pragma unroll
        for (int ksv = 0; ksv < 4; ksv++) {
            const float* gp = g_gparts + (size_t)ksv * (Bv * G4H);
            gi += gp[base + h];
            gf += gp[base + 1024 + h];
            gg += gp[base + 2048 + h];
            go += gp[base + 3072 + h];
        }
        gi += b_ih[h]        + b_hh[h];
        gf += b_ih[1024 + h] + b_hh[1024 + h];
        gg += b_ih[2048 + h] + b_hh[2048 + h];
        go += b_ih[3072 + h] + b_hh[3072 + h];
        float si = 1.f / (1.f + expf(-gi));
        float sf = 1.f / (1.f + expf(-gf));
        float so = 1.f / (1.f + expf(-go));
        float c  = sf * cell[b * Hv + h] + si * tanhf(gg);
        float hn = so * tanhf(c);
        c_out[b * Hv + h] = c;
        h_out[b * Hv + h] = hn;
    }
}

// =============================================================
// Kernel 5: vocab GEMM  pred[64 x 50257] = h_next * Wf^T + bf
// BN=128, BK=32, 256 thr, 4b x 8v register tiles, K-major smem.
// =============================================================
__global__ void __launch_bounds__(256) vocab_gemm(
    const float* __restrict__ h_next, const float* __restrict__ Wf,
    const float* __restrict__ bf, float* __restrict__ pred)
{
    const int vt = blockIdx.x;
    const int t  = threadIdx.x;
    __shared__ float hs[32][68];
    __shared__ float ws[32][136];
    const int tb = (t & 15) * 4;
    const int tv = (t >> 4) * 8;
    float acc[4][8] = {};
    const int vbase = vt * 128;

    for (int kc = 0; kc < 32; kc++) {
        const int kbase = kc * 32;
#pragma unroll
        for (int i = 0; i < 8; i++) {
            int e = t + 256 * i;
            int bb = e >> 5, kk = e & 31;
            hs[kk][bb] = h_next[bb * Hv + kbase + kk];
        }
#pragma unroll
        for (int i = 0; i < 16; i++) {
            int e = t + 256 * i;
            int vv = e >> 5, kk = e & 31;
            int vg = vbase + vv;
            ws[kk][vv] = (vg < Vv) ? Wf[(size_t)vg * Hv + kbase + kk] : 0.f;
        }
        __syncthreads();
#pragma unroll
        for (int kk = 0; kk < 32; kk++) {
            float4 hr = *(const float4*)&hs[kk][tb];
            float4 w0 = *(const float4*)&ws[kk][tv];
            float4 w1 = *(const float4*)&ws[kk][tv + 4];
            float hv[4] = {hr.x, hr.y, hr.z, hr.w};
            float wv[8] = {w0.x, w0.y, w0.z, w0.w, w1.x, w1.y, w1.z, w1.w};
#pragma unroll
            for (int i = 0; i < 4; i++)
#pragma unroll
                for (int j = 0; j < 8; j++) acc[i][j] += hv[i] * wv[j];
        }
        __syncthreads();
    }
#pragma unroll
    for (int i = 0; i < 4; i++) {
        const int bb = tb + i;
#pragma unroll
        for (int j = 0; j < 8; j++) {
            int vg = vbase + tv + j;
            if (vg < Vv) pred[(size_t)bb * Vv + vg] = acc[i][j] + bf[vg];
        }
    }
}

// =============================================================
extern "C" void kernel_launch(void* const* d_in, const int* in_sizes, int n_in,
                              void* d_out, int out_size)
{
    const float* enc    = (const float*)d_in[0];
    const int*   x_tok  = (const int*)  d_in[1];
    const float* hidden = (const float*)d_in[2];
    const float* cell   = (const float*)d_in[3];
    const float* emb    = (const float*)d_in[4];
    const float* We     = (const float*)d_in[5];
    const float* be     = (const float*)d_in[6];
    const float* W_ih   = (const float*)d_in[7];
    const float* W_hh   = (const float*)d_in[8];
    const float* b_ih   = (const float*)d_in[9];
    const float* b_hh   = (const float*)d_in[10];
    const float* Wf     = (const float*)d_in[11];
    const float* bf     = (const float*)d_in[12];

    float* out   = (float*)d_out;
    float* pred  = out;                          // [B, V]
    float* h_out = out + (size_t)Bv * Vv;        // [B, H]

    attn_kernel   <<<dim3(SPLITS, Bv), 256>>>(enc, hidden, We, be);
    combine_kernel<<<Bv, 256>>>(hidden, emb, x_tok);
    gates_gemm    <<<dim3(64, 4), 256>>>(W_ih, W_hh);
    lstm_kernel   <<<Bv, 256>>>(cell, b_ih, b_hh, out);
    vocab_gemm    <<<(Vv + 127) / 128, 256>>>(h_out, Wf, bf, pred);
}

// round 4
// speedup vs baseline: 2.5544x; 2.5544x over previous
#include <cuda_runtime.h>
#include <cuda_bf16.h>
#include <cstdint>
#include <math.h>

#define Bv   64
#define Sv   1024
#define Hv   1024
#define Ev   512
#define Vv   50257
#define D2H  2048
#define XK   3584   // 2H + E + H
#define G4H  4096
#define SPLITS 16

// ---------------- scratch (device globals; no runtime allocation) ----------
__device__ float g_partial_l[Bv * SPLITS];
__device__ float g_partial_acc[(size_t)Bv * SPLITS * D2H];   // 8 MB
__device__ float g_xfull[Bv * XK];
__device__ float g_gparts[4 * (size_t)Bv * G4H];              // 4 MB

// =================== helpers (base PTX only, no sm_103a features) ==========
__device__ __forceinline__ uint32_t smem_u32(const void* p) {
    uint32_t a;
    asm("{ .reg .u64 tmp; cvta.to.shared.u64 tmp, %1; cvt.u32.u64 %0, tmp; }"
        : "=r"(a) : "l"(p));
    return a;
}
__device__ __forceinline__ uint32_t lds32(uint32_t addr) {
    uint32_t v;
    asm volatile("ld.shared.b32 %0, [%1];" : "=r"(v) : "r"(addr));
    return v;
}
__device__ __forceinline__ void sts_v2(uint32_t addr, uint32_t a, uint32_t b) {
    asm volatile("st.shared.v2.b32 [%0], {%1, %2};" :: "r"(addr), "r"(a), "r"(b));
}
__device__ __forceinline__ void sts32f(uint32_t addr, float v) {
    asm volatile("st.shared.f32 [%0], %1;" :: "r"(addr), "f"(v));
}
__device__ __forceinline__ float4 lds128f(uint32_t addr) {
    float4 v;
    asm volatile("ld.shared.v4.f32 {%0,%1,%2,%3}, [%4];"
        : "=f"(v.x), "=f"(v.y), "=f"(v.z), "=f"(v.w) : "r"(addr));
    return v;
}
__device__ __forceinline__ uint32_t sw128(uint32_t off) {
    return off ^ ((off >> 3) & 0x70);
}
// m16n8k16 bf16 MMA, f32 accum (base PTX, sm_80+)
__device__ __forceinline__ void hmma(float* c, const uint32_t* a, const uint32_t* b) {
    asm volatile(
        "mma.sync.aligned.m16n8k16.row.col.f32.bf16.bf16.f32 "
        "{%0,%1,%2,%3}, {%4,%5,%6,%7}, {%8,%9}, {%0,%1,%2,%3};"
        : "+f"(c[0]), "+f"(c[1]), "+f"(c[2]), "+f"(c[3])
        : "r"(a[0]), "r"(a[1]), "r"(a[2]), "r"(a[3]), "r"(b[0]), "r"(b[1]));
}
// fp32x4 -> bf16 hi pair + lo (residual) pair
__device__ __forceinline__ void split4(float4 v, uint32_t& ha, uint32_t& hb,
                                       uint32_t& la, uint32_t& lb) {
    asm("cvt.rn.bf16x2.f32 %0, %1, %2;" : "=r"(ha) : "f"(v.y), "f"(v.x));
    asm("cvt.rn.bf16x2.f32 %0, %1, %2;" : "=r"(hb) : "f"(v.w), "f"(v.z));
    float rx = v.x - __uint_as_float(ha << 16);
    float ry = v.y - __uint_as_float(ha & 0xffff0000u);
    float rz = v.z - __uint_as_float(hb << 16);
    float rw = v.w - __uint_as_float(hb & 0xffff0000u);
    asm("cvt.rn.bf16x2.f32 %0, %1, %2;" : "=r"(la) : "f"(ry), "f"(rx));
    asm("cvt.rn.bf16x2.f32 %0, %1, %2;" : "=r"(lb) : "f"(rw), "f"(rz));
}

// smem tile layout (bytes from aligned dynamic base)
#define T_A_HI 0
#define T_A_LO 16384
#define T_B_HI 32768
#define T_B_LO 40960
#define SMEM_DYN 49408
// epilogue transpose row stride: 132 floats = 528 bytes (16B-aligned)
#define EPI_STRIDE 528

// =============================================================
// Kernel 1: attention. grid (SPLITS, B), 256 thr. 8-row tiles,
// single streaming pass, unnormalized softmax (relu energy >= 0,
// bounded; exp safe).
// =============================================================
__global__ void __launch_bounds__(256) attn_kernel(
    const float* __restrict__ enc, const float* __restrict__ hidden,
    const float* __restrict__ We, const float* __restrict__ be_p)
{
    const int b = blockIdx.y, sp = blockIdx.x, t = threadIdx.x;
    const int lane = t & 31, wid = t >> 5;
    __shared__ float red[8][8];
    __shared__ float redh[8];

    const float4* We4  = (const float4*)We;
    const float4* hid4 = (const float4*)hidden;
    const float4 w0 = We4[t];
    const float4 w1 = We4[256 + t];

    {
        float4 hv = hid4[b * 256 + t];
        float4 wv = We4[512 + t];
        float p = hv.x * wv.x + hv.y * wv.y + hv.z * wv.z + hv.w * wv.w;
#pragma unroll
        for (int o = 16; o > 0; o >>= 1) p += __shfl_xor_sync(0xffffffffu, p, o);
        if (lane == 0) redh[wid] = p;
    }
    __syncthreads();
    float hb = be_p[0];
#pragma unroll
    for (int w = 0; w < 8; w++) hb += redh[w];

    float acc[8] = {0.f, 0.f, 0.f, 0.f, 0.f, 0.f, 0.f, 0.f};
    float lsum = 0.f;
    const float4* encb = (const float4*)enc + ((size_t)(b * Sv + sp * 64)) * 512;

    for (int tile = 0; tile < 8; tile++) {
        const float4* tbase = encb + (size_t)tile * 8 * 512;
        float4 ev0[8], ev1[8];
#pragma unroll
        for (int r = 0; r < 8; r++) {
            ev0[r] = tbase[r * 512 + t];
            ev1[r] = tbase[r * 512 + 256 + t];
        }
        float d[8];
#pragma unroll
        for (int r = 0; r < 8; r++) {
            d[r] = ev0[r].x * w0.x + ev0[r].y * w0.y + ev0[r].z * w0.z + ev0[r].w * w0.w
                 + ev1[r].x * w1.x + ev1[r].y * w1.y + ev1[r].z * w1.z + ev1[r].w * w1.w;
#pragma unroll
            for (int o = 16; o > 0; o >>= 1) d[r] += __shfl_xor_sync(0xffffffffu, d[r], o);
        }
        if (lane == 0) {
#pragma unroll
            for (int r = 0; r < 8; r++) red[wid][r] = d[r];
        }
        __syncthreads();
        float wgt[8];
#pragma unroll
        for (int r = 0; r < 8; r++) {
            float s = hb;
#pragma unroll
            for (int w = 0; w < 8; w++) s += red[w][r];
            s = fmaxf(s, 0.f);
            wgt[r] = __expf(s);
            lsum += wgt[r];
        }
        __syncthreads();
#pragma unroll
        for (int r = 0; r < 8; r++) {
            acc[0] += wgt[r] * ev0[r].x;  acc[1] += wgt[r] * ev0[r].y;
            acc[2] += wgt[r] * ev0[r].z;  acc[3] += wgt[r] * ev0[r].w;
            acc[4] += wgt[r] * ev1[r].x;  acc[5] += wgt[r] * ev1[r].y;
            acc[6] += wgt[r] * ev1[r].z;  acc[7] += wgt[r] * ev1[r].w;
        }
    }
    float4* pacc = (float4*)(g_partial_acc + ((size_t)(b * SPLITS + sp)) * D2H);
    pacc[t]       = make_float4(acc[0], acc[1], acc[2], acc[3]);
    pacc[256 + t] = make_float4(acc[4], acc[5], acc[6], acc[7]);
    if (t == 0) g_partial_l[b * SPLITS + sp] = lsum;
}

// =============================================================
// Kernel 2: combine partials -> c_i; build x_full. grid (8, B).
// =============================================================
__global__ void __launch_bounds__(256) combine_kernel(
    const float* __restrict__ hidden, const float* __restrict__ emb,
    const int* __restrict__ x_tok)
{
    const int q = blockIdx.x, b = blockIdx.y, t = threadIdx.x;
    float s = 0.f;
#pragma unroll
    for (int i = 0; i < SPLITS; i++) s += g_partial_l[b * SPLITS + i];
    const float inv = 1.f / s;
    const int c = q * 256 + t;
    float a = 0.f;
#pragma unroll
    for (int i = 0; i < SPLITS; i++)
        a += g_partial_acc[((size_t)(b * SPLITS + i)) * D2H + c];
    g_xfull[b * XK + c] = a * inv;
    if (q == 0) {
        const int tok = x_tok[b];
        for (int j = t; j < Ev; j += 256)
            g_xfull[b * XK + D2H + j] = emb[(size_t)tok * Ev + j];
        for (int j = t; j < Hv; j += 256)
            g_xfull[b * XK + D2H + Ev + j] = hidden[b * Hv + j];
    }
}

// ============= shared MMA mainloop pieces (device inline) ===============
__device__ __forceinline__ void frag_a(uint32_t tile, int w, int g, int tg,
                                       int ks, uint32_t a[4]) {
    uint32_t r0 = (uint32_t)(16 * w + g);
    uint32_t k0 = (uint32_t)((16 * ks + 2 * tg) * 2);
    a[0] = lds32(tile + sw128(r0 * 128 + k0));
    a[1] = lds32(tile + sw128((r0 + 8) * 128 + k0));
    a[2] = lds32(tile + sw128(r0 * 128 + k0 + 16));
    a[3] = lds32(tile + sw128((r0 + 8) * 128 + k0 + 16));
}
__device__ __forceinline__ void frag_b(uint32_t tile, int j, int g, int tg,
                                       int ks, uint32_t bfr[2]) {
    uint32_t n = (uint32_t)(8 * j + g);
    uint32_t k0 = (uint32_t)((16 * ks + 2 * tg) * 2);
    bfr[0] = lds32(tile + sw128(n * 128 + k0));
    bfr[1] = lds32(tile + sw128(n * 128 + k0 + 16));
}

// =============================================================
// Kernel 3: gates GEMM (HMMA split-bf16). grid (32 gate-tiles, 4 K-splits).
// =============================================================
__global__ void __launch_bounds__(256) gates_mma(
    const float* __restrict__ W_ih, const float* __restrict__ W_hh)
{
    extern __shared__ char dsm[];
    const uint32_t sb = (smem_u32(dsm) + 127u) & ~127u;
    const int t = threadIdx.x, w = t >> 5, lane = t & 31;
    const int g = lane >> 2, tg = lane & 3;
    const int gbase = blockIdx.x * 128;
    const int ks_split = blockIdx.y;

    float acc[8][4] = {};
    float4 aP[8], bP[4];

    {
        const int kg = ks_split * 896;
        const bool ih = (kg < 2560);
#pragma unroll
        for (int i = 0; i < 8; i++) {
            int e = i * 256 + t, row = e >> 4, c4 = e & 15;
            int og = gbase + row;
            aP[i] = ih ? *(const float4*)(W_ih + (size_t)og * 2560 + kg + c4 * 4)
                       : *(const float4*)(W_hh + (size_t)og * 1024 + (kg - 2560) + c4 * 4);
        }
#pragma unroll
        for (int i = 0; i < 4; i++) {
            int e = i * 256 + t, row = e >> 4, c4 = e & 15;
            bP[i] = *(const float4*)(g_xfull + (size_t)row * XK + kg + c4 * 4);
        }
    }

    for (int ch = 0; ch < 14; ch++) {
        __syncthreads();
#pragma unroll
        for (int i = 0; i < 8; i++) {
            int e = i * 256 + t, row = e >> 4, c4 = e & 15;
            uint32_t ha, hb2, la, lb; split4(aP[i], ha, hb2, la, lb);
            uint32_t off = sw128((uint32_t)(row * 128 + c4 * 8));
            sts_v2(sb + T_A_HI + off, ha, hb2);
            sts_v2(sb + T_A_LO + off, la, lb);
        }
#pragma unroll
        for (int i = 0; i < 4; i++) {
            int e = i * 256 + t, row = e >> 4, c4 = e & 15;
            uint32_t ha, hb2, la, lb; split4(bP[i], ha, hb2, la, lb);
            uint32_t off = sw128((uint32_t)(row * 128 + c4 * 8));
            sts_v2(sb + T_B_HI + off, ha, hb2);
            sts_v2(sb + T_B_LO + off, la, lb);
        }
        __syncthreads();
        if (ch + 1 < 14) {
            const int kg = ks_split * 896 + (ch + 1) * 64;
            const bool ih = (kg < 2560);
#pragma unroll
            for (int i = 0; i < 8; i++) {
                int e = i * 256 + t, row = e >> 4, c4 = e & 15;
                int og = gbase + row;
                aP[i] = ih ? *(const float4*)(W_ih + (size_t)og * 2560 + kg + c4 * 4)
                           : *(const float4*)(W_hh + (size_t)og * 1024 + (kg - 2560) + c4 * 4);
            }
#pragma unroll
            for (int i = 0; i < 4; i++) {
                int e = i * 256 + t, row = e >> 4, c4 = e & 15;
                bP[i] = *(const float4*)(g_xfull + (size_t)row * XK + kg + c4 * 4);
            }
        }
#pragma unroll
        for (int ks = 0; ks < 4; ks++) {
            uint32_t ahi[4], alo[4];
            frag_a(sb + T_A_HI, w, g, tg, ks, ahi);
            frag_a(sb + T_A_LO, w, g, tg, ks, alo);
#pragma unroll
            for (int jh = 0; jh < 2; jh++) {
                uint32_t bh[4][2], bl[4][2];
#pragma unroll
                for (int jj = 0; jj < 4; jj++) {
                    frag_b(sb + T_B_HI, jh * 4 + jj, g, tg, ks, bh[jj]);
                    frag_b(sb + T_B_LO, jh * 4 + jj, g, tg, ks, bl[jj]);
                }
#pragma unroll
                for (int jj = 0; jj < 4; jj++) hmma(acc[jh * 4 + jj], ahi, bh[jj]);
#pragma unroll
                for (int jj = 0; jj < 4; jj++) hmma(acc[jh * 4 + jj], alo, bh[jj]);
#pragma unroll
                for (int jj = 0; jj < 4; jj++) hmma(acc[jh * 4 + jj], ahi, bl[jj]);
            }
        }
    }
    // epilogue: transpose through smem (528B stride) -> coalesced float4 STG
    __syncthreads();
#pragma unroll
    for (int j = 0; j < 8; j++) {
#pragma unroll
        for (int k = 0; k < 4; k++) {
            int bb = 8 * j + 2 * tg + (k & 1);
            int vl = 16 * w + g + ((k >> 1) ? 8 : 0);
            sts32f(sb + (uint32_t)(bb * EPI_STRIDE + vl * 4), acc[j][k]);
        }
    }
    __syncthreads();
    float* gp = g_gparts + (size_t)ks_split * (Bv * G4H);
#pragma unroll
    for (int i = 0; i < 8; i++) {
        int e = i * 256 + t, bb = e >> 5, c4 = e & 31;
        float4 v = lds128f(sb + (uint32_t)(bb * EPI_STRIDE + c4 * 16));
        *(float4*)(gp + (size_t)bb * G4H + gbase + c4 * 4) = v;
    }
}

// =============================================================
// Kernel 4: split-K sum + biases + LSTM pointwise. grid (4, B).
// =============================================================
__global__ void __launch_bounds__(256) lstm_kernel(
    const float* __restrict__ cell, const float* __restrict__ b_ih,
    const float* __restrict__ b_hh, float* __restrict__ out)
{
    const int b = blockIdx.y, h = blockIdx.x * 256 + threadIdx.x;
    float* h_out = out + (size_t)Bv * Vv;
    float* c_out = h_out + Bv * Hv;
    const int base = b * G4H;
    float gi = 0.f, gf = 0.f, gg = 0.f, go = 0.f;
#pragma unroll
    for (int ksv = 0; ksv < 4; ksv++) {
        const float* gp = g_gparts + (size_t)ksv * (Bv * G4H);
        gi += gp[base + h];
        gf += gp[base + 1024 + h];
        gg += gp[base + 2048 + h];
        go += gp[base + 3072 + h];
    }
    gi += b_ih[h]        + b_hh[h];
    gf += b_ih[1024 + h] + b_hh[1024 + h];
    gg += b_ih[2048 + h] + b_hh[2048 + h];
    go += b_ih[3072 + h] + b_hh[3072 + h];
    float si = 1.f / (1.f + expf(-gi));
    float sf = 1.f / (1.f + expf(-gf));
    float so = 1.f / (1.f + expf(-go));
    float c  = sf * cell[b * Hv + h] + si * tanhf(gg);
    float hn = so * tanhf(c);
    c_out[b * Hv + h] = c;
    h_out[b * Hv + h] = hn;
}

// =============================================================
// Kernel 5: vocab GEMM (HMMA split-bf16). grid (393).
// =============================================================
__global__ void __launch_bounds__(256) vocab_mma(
    const float* __restrict__ Wf, const float* __restrict__ h,
    const float* __restrict__ bf, float* __restrict__ pred)
{
    extern __shared__ char dsm[];
    const uint32_t sb = (smem_u32(dsm) + 127u) & ~127u;
    const int t = threadIdx.x, w = t >> 5, lane = t & 31;
    const int g = lane >> 2, tg = lane & 3;
    const int vbase = blockIdx.x * 128;

    float acc[8][4] = {};
    float4 aP[8], bP[4];

#pragma unroll
    for (int i = 0; i < 8; i++) {
        int e = i * 256 + t, row = e >> 4, c4 = e & 15;
        int vg = vbase + row;
        aP[i] = (vg < Vv) ? *(const float4*)(Wf + (size_t)vg * Hv + c4 * 4)
                          : make_float4(0.f, 0.f, 0.f, 0.f);
    }
#pragma unroll
    for (int i = 0; i < 4; i++) {
        int e = i * 256 + t, row = e >> 4, c4 = e & 15;
        bP[i] = *(const float4*)(h + (size_t)row * Hv + c4 * 4);
    }

    for (int ch = 0; ch < 16; ch++) {
        __syncthreads();
#pragma unroll
        for (int i = 0; i < 8; i++) {
            int e = i * 256 + t, row = e >> 4, c4 = e & 15;
            uint32_t ha, hb2, la, lb; split4(aP[i], ha, hb2, la, lb);
            uint32_t off = sw128((uint32_t)(row * 128 + c4 * 8));
            sts_v2(sb + T_A_HI + off, ha, hb2);
            sts_v2(sb + T_A_LO + off, la, lb);
        }
#pragma unroll
        for (int i = 0; i < 4; i++) {
            int e = i * 256 + t, row = e >> 4, c4 = e & 15;
            uint32_t ha, hb2, la, lb; split4(bP[i], ha, hb2, la, lb);
            uint32_t off = sw128((uint32_t)(row * 128 + c4 * 8));
            sts_v2(sb + T_B_HI + off, ha, hb2);
            sts_v2(sb + T_B_LO + off, la, lb);
        }
        __syncthreads();
        if (ch + 1 < 16) {
            const int kb = (ch + 1) * 64;
#pragma unroll
            for (int i = 0; i < 8; i++) {
                int e = i * 256 + t, row = e >> 4, c4 = e & 15;
                int vg = vbase + row;
                aP[i] = (vg < Vv) ? *(const float4*)(Wf + (size_t)vg * Hv + kb + c4 * 4)
                                  : make_float4(0.f, 0.f, 0.f, 0.f);
            }
#pragma unroll
            for (int i = 0; i < 4; i++) {
                int e = i * 256 + t, row = e >> 4, c4 = e & 15;
                bP[i] = *(const float4*)(h + (size_t)row * Hv + kb + c4 * 4);
            }
        }
#pragma unroll
        for (int ks = 0; ks < 4; ks++) {
            uint32_t ahi[4], alo[4];
            frag_a(sb + T_A_HI, w, g, tg, ks, ahi);
            frag_a(sb + T_A_LO, w, g, tg, ks, alo);
#pragma unroll
            for (int jh = 0; jh < 2; jh++) {
                uint32_t bh[4][2], bl[4][2];
#pragma unroll
                for (int jj = 0; jj < 4; jj++) {
                    frag_b(sb + T_B_HI, jh * 4 + jj, g, tg, ks, bh[jj]);
                    frag_b(sb + T_B_LO, jh * 4 + jj, g, tg, ks, bl[jj]);
                }
#pragma unroll
                for (int jj = 0; jj < 4; jj++) hmma(acc[jh * 4 + jj], ahi, bh[jj]);
#pragma unroll
                for (int jj = 0; jj < 4; jj++) hmma(acc[jh * 4 + jj], alo, bh[jj]);
#pragma unroll
                for (int jj = 0; jj < 4; jj++) hmma(acc[jh * 4 + jj], ahi, bl[jj]);
            }
        }
    }
    // epilogue: transpose via smem (528B stride), add bias, scalar STG
    // (pred row stride Vv=50257 is not 16B-aligned, so no float4 on gmem).
    __syncthreads();
#pragma unroll
    for (int j = 0; j < 8; j++) {
#pragma unroll
        for (int k = 0; k < 4; k++) {
            int bb = 8 * j + 2 * tg + (k & 1);
            int vl = 16 * w + g + ((k >> 1) ? 8 : 0);
            sts32f(sb + (uint32_t)(bb * EPI_STRIDE + vl * 4), acc[j][k]);
        }
    }
    __syncthreads();
#pragma unroll
    for (int i = 0; i < 8; i++) {
        int e = i * 256 + t, bb = e >> 5, c4 = e & 31;
        float4 v = lds128f(sb + (uint32_t)(bb * EPI_STRIDE + c4 * 16));
        int vg = vbase + c4 * 4;
        float* prow = pred + (size_t)bb * Vv;
        float vv[4] = {v.x, v.y, v.z, v.w};
#pragma unroll
        for (int d = 0; d < 4; d++)
            if (vg + d < Vv) prow[vg + d] = vv[d] + bf[vg + d];
    }
}

// =============================================================
extern "C" void kernel_launch(void* const* d_in, const int* in_sizes, int n_in,
                              void* d_out, int out_size)
{
    const float* enc    = (const float*)d_in[0];
    const int*   x_tok  = (const int*)  d_in[1];
    const float* hidden = (const float*)d_in[2];
    const float* cell   = (const float*)d_in[3];
    const float* emb    = (const float*)d_in[4];
    const float* We     = (const float*)d_in[5];
    const float* be     = (const float*)d_in[6];
    const float* W_ih   = (const float*)d_in[7];
    const float* W_hh   = (const float*)d_in[8];
    const float* b_ih   = (const float*)d_in[9];
    const float* b_hh   = (const float*)d_in[10];
    const float* Wf     = (const float*)d_in[11];
    const float* bf     = (const float*)d_in[12];

    float* out   = (float*)d_out;
    float* pred  = out;                          // [B, V]
    float* h_out = out + (size_t)Bv * Vv;        // [B, H]

    cudaFuncSetAttribute(gates_mma, cudaFuncAttributeMaxDynamicSharedMemorySize, SMEM_DYN);
    cudaFuncSetAttribute(vocab_mma, cudaFuncAttributeMaxDynamicSharedMemorySize, SMEM_DYN);

    attn_kernel   <<<dim3(SPLITS, Bv), 256>>>(enc, hidden, We, be);
    combine_kernel<<<dim3(8, Bv), 256>>>(hidden, emb, x_tok);
    gates_mma     <<<dim3(32, 4), 256, SMEM_DYN>>>(W_ih, W_hh);
    lstm_kernel   <<<dim3(4, Bv), 256>>>(cell, b_ih, b_hh, out);
    vocab_mma     <<<(Vv + 127) / 128, 256, SMEM_DYN>>>(Wf, h_out, bf, pred);
}